// round 1
// baseline (speedup 1.0000x reference)
#include <cuda_runtime.h>

// Problem constants
#define B_DIM 128
#define T_DIM 256
#define D_DIM 32
#define N_DIM 64

// Scratch (device globals: no allocation allowed)
__device__ float g_aBuf[D_DIM * T_DIM * B_DIM];   // [i][t][b] unnormalized alphas
__device__ float g_denBuf[D_DIM * B_DIM];         // [i][b]
__device__ float g_gBuf[B_DIM * D_DIM * N_DIM];   // [b][i][k] g_n (normalized)
__device__ float g_hTBuf[B_DIM * D_DIM * N_DIM];  // [b][i][k] h_T

// ---------------- math helpers ----------------
static __device__ __forceinline__ float fsig(float x) {
    return __fdividef(1.0f, 1.0f + __expf(-x));
}
static __device__ __forceinline__ float ftanh_(float x) {
    float ax = fabsf(x);
    float e = __expf(-2.0f * ax);
    float t = 1.0f - __fdividef(2.0f * e, 1.0f + e);
    return copysignf(t, x);
}
// packed f32x2 fma (Blackwell sm_100+)
static __device__ __forceinline__ void fma2(unsigned long long& a,
                                            unsigned long long b,
                                            unsigned long long c) {
    asm("fma.rn.f32x2 %0, %1, %2, %0;" : "+l"(a) : "l"(b), "l"(c));
}
static __device__ __forceinline__ unsigned long long pack2(float x) {
    unsigned long long r;
    asm("mov.b64 %0, {%1, %1};" : "=l"(r) : "f"(x));
    return r;
}
static __device__ __forceinline__ float2 unpack2(unsigned long long a) {
    float lo, hi;
    asm("mov.b64 {%0, %1}, %2;" : "=f"(lo), "=f"(hi) : "l"(a));
    return make_float2(lo, hi);
}

// ---------------- shared memory layout (float offsets) ----------------
#define SM_W   0        // 4 gates * 64 j * 64 k = 16384 floats (gate-major, row j, col k)
#define SM_U   16384    // 4 * 64
#define SM_B   16640    // 4 * 64
#define SM_FA  16896    // 64
#define SM_X   16960    // 256 t * 32 b = 8192
#define SM_H   25152    // 64 k * 32 b = 2048
#define SM_SP  27200    // 8 g * 32 b = 256
#define SM_TOT 27456    // floats -> 109824 bytes

// ===================== Kernel 1: fused LSTM recurrence + streamed attention =====================
// grid = (32 i, 4 b-chunks), block = 256 threads: g = tid>>5 (k-group of 8), bl = tid&31 (local b)
__global__ void __launch_bounds__(256)
lstm_kernel(const float* __restrict__ x,
            const float* __restrict__ Uj, const float* __restrict__ Ui_,
            const float* __restrict__ Uf, const float* __restrict__ Uo,
            const float* __restrict__ Wj, const float* __restrict__ Wi_,
            const float* __restrict__ Wf, const float* __restrict__ Wo,
            const float* __restrict__ bj, const float* __restrict__ bi_,
            const float* __restrict__ bf, const float* __restrict__ bo,
            const float* __restrict__ Fa, const float* __restrict__ Fab) {
    extern __shared__ float sm[];
    const int tid = threadIdx.x;
    const int g   = tid >> 5;
    const int bl  = tid & 31;
    const int i   = blockIdx.x;
    const int b0  = blockIdx.y << 5;
    const int b   = b0 + bl;
    const int k0  = g << 3;

    // ---- cooperative loads ----
    {
        const float* Wg[4] = {Wj, Wi_, Wf, Wo};
#pragma unroll
        for (int gg = 0; gg < 4; gg++) {
            const float* src = Wg[gg];
            for (int idx = tid; idx < 4096; idx += 256) {
                int j = idx >> 6, k = idx & 63;
                sm[SM_W + gg * 4096 + idx] = src[(j * 32 + i) * 64 + k];
            }
        }
        const float* Ug[4] = {Uj, Ui_, Uf, Uo};
        const float* Bg[4] = {bj, bi_, bf, bo};
        if (tid < 64) {
#pragma unroll
            for (int gg = 0; gg < 4; gg++) {
                sm[SM_U + gg * 64 + tid] = Ug[gg][i * 64 + tid];
                sm[SM_B + gg * 64 + tid] = Bg[gg][i * 64 + tid];
            }
            sm[SM_FA + tid] = Fa[tid * 32 + i];  // F_alpha_n[j, i, 0]
        }
        for (int idx = tid; idx < 8192; idx += 256) {
            int t = idx >> 5, blx = idx & 31;
            sm[SM_X + idx] = x[((b0 + blx) * 256 + t) * 32 + i];
        }
        for (int idx = tid; idx < 2048; idx += 256) sm[SM_H + idx] = 0.0f;
    }
    const float FabV = Fab[i];
    __syncthreads();

    // ---- state ----
    unsigned long long acc[16];
    float c[8], gacc[8], hn[8];
    float den = 0.0f;
#pragma unroll
    for (int kk = 0; kk < 8; kk++) { c[kk] = 0.0f; gacc[kk] = 0.0f; hn[kk] = 0.0f; }

    const ulonglong2* W2 = (const ulonglong2*)(sm + SM_W);   // 16B units; gate stride 1024
    const ulonglong2* U2 = (const ulonglong2*)(sm + SM_U);
    const ulonglong2* B2 = (const ulonglong2*)(sm + SM_B);
    const float* hP = sm + SM_H;
    const int kq = k0 >> 2;  // ull2 offset within a 64-float row

    for (int t = 0; t < 256; t++) {
        const float xv = sm[SM_X + t * 32 + bl];
        const unsigned long long xv2 = pack2(xv);

        // acc = bias + xv * U   (packed)
#pragma unroll
        for (int gg = 0; gg < 4; gg++) {
            int o = gg * 16 + kq;
            ulonglong2 u0 = U2[o], u1 = U2[o + 1];
            ulonglong2 bb0 = B2[o], bb1 = B2[o + 1];
            acc[gg * 4 + 0] = bb0.x; fma2(acc[gg * 4 + 0], u0.x, xv2);
            acc[gg * 4 + 1] = bb0.y; fma2(acc[gg * 4 + 1], u0.y, xv2);
            acc[gg * 4 + 2] = bb1.x; fma2(acc[gg * 4 + 2], u1.x, xv2);
            acc[gg * 4 + 3] = bb1.y; fma2(acc[gg * 4 + 3], u1.y, xv2);
        }

        // recurrent matvec: acc[k] += sum_j h[j] * W[j,k], 4 gates
#pragma unroll 4
        for (int j = 0; j < 64; j++) {
            const unsigned long long h2 = pack2(hP[j * 32 + bl]);
            const int rb = j * 16 + kq;
            ulonglong2 w;
            w = W2[rb];          fma2(acc[0],  w.x, h2); fma2(acc[1],  w.y, h2);
            w = W2[rb + 1];      fma2(acc[2],  w.x, h2); fma2(acc[3],  w.y, h2);
            w = W2[rb + 1024];   fma2(acc[4],  w.x, h2); fma2(acc[5],  w.y, h2);
            w = W2[rb + 1025];   fma2(acc[6],  w.x, h2); fma2(acc[7],  w.y, h2);
            w = W2[rb + 2048];   fma2(acc[8],  w.x, h2); fma2(acc[9],  w.y, h2);
            w = W2[rb + 2049];   fma2(acc[10], w.x, h2); fma2(acc[11], w.y, h2);
            w = W2[rb + 3072];   fma2(acc[12], w.x, h2); fma2(acc[13], w.y, h2);
            w = W2[rb + 3073];   fma2(acc[14], w.x, h2); fma2(acc[15], w.y, h2);
        }

        // gate nonlinearities + state update + alpha-score partial
        float sp = 0.0f;
#pragma unroll
        for (int p = 0; p < 4; p++) {
            float2 jv = unpack2(acc[p]);
            float2 iv = unpack2(acc[4 + p]);
            float2 fv = unpack2(acc[8 + p]);
            float2 ov = unpack2(acc[12 + p]);
            {
                int kk = 2 * p;
                float jj = ftanh_(jv.x), ii = fsig(iv.x), ff = fsig(fv.x), oo = fsig(ov.x);
                float cn = fmaf(c[kk], ff, ii * jj);
                c[kk] = cn;
                float hh = oo * ftanh_(cn);
                hn[kk] = hh;
                sp = fmaf(hh, sm[SM_FA + k0 + kk], sp);
            }
            {
                int kk = 2 * p + 1;
                float jj = ftanh_(jv.y), ii = fsig(iv.y), ff = fsig(fv.y), oo = fsig(ov.y);
                float cn = fmaf(c[kk], ff, ii * jj);
                c[kk] = cn;
                float hh = oo * ftanh_(cn);
                hn[kk] = hh;
                sp = fmaf(hh, sm[SM_FA + k0 + kk], sp);
            }
        }

        __syncthreads();  // all reads of sm_H for this step done
#pragma unroll
        for (int kk = 0; kk < 8; kk++) sm[SM_H + (k0 + kk) * 32 + bl] = hn[kk];
        sm[SM_SP + g * 32 + bl] = sp;
        __syncthreads();  // new h + score partials visible

        float s = FabV;
#pragma unroll
        for (int gg = 0; gg < 8; gg++) s += sm[SM_SP + gg * 32 + bl];
        float av = __expf(ftanh_(s));
        den += av;
#pragma unroll
        for (int kk = 0; kk < 8; kk++) gacc[kk] = fmaf(av, hn[kk], gacc[kk]);
        if (g == 0) g_aBuf[(i * 256 + t) * 128 + b] = av;
    }

    // ---- epilogue: write g_n (normalized) and h_T ----
    float invd = __fdividef(1.0f, den);
#pragma unroll
    for (int kk = 0; kk < 8; kk++) {
        g_gBuf[(b * 32 + i) * 64 + k0 + kk]  = gacc[kk] * invd;
        g_hTBuf[(b * 32 + i) * 64 + k0 + kk] = hn[kk];
    }
    if (g == 0) g_denBuf[i * 128 + b] = den;
}

// ===================== Kernel 2: normalize alphas into output layout [B,T,D] =====================
__global__ void alpha_kernel(float* __restrict__ out) {
    int idx = blockIdx.x * 256 + threadIdx.x;  // 0 .. 1048575
    int b = idx >> 13;          // / (T*D)
    int r = idx & 8191;
    int t = r >> 5;             // / D
    int i = r & 31;
    float a = g_aBuf[(i * 256 + t) * 128 + b];
    float d = g_denBuf[i * 128 + b];
    out[128 + idx] = __fdividef(a, d);
}

// ===================== Kernel 3: output head (mu, betas, mean) =====================
__global__ void head_kernel(float* __restrict__ out,
                            const float* __restrict__ Phi_w, const float* __restrict__ Phi_b,
                            const float* __restrict__ Fbw, const float* __restrict__ Fbb) {
    int b = blockIdx.x;   // 128 blocks
    int i = threadIdx.x;  // 32 threads = D
    const float* gp = g_gBuf + (b * 32 + i) * 64;
    const float* hp = g_hTBuf + (b * 32 + i) * 64;
    float mu = Phi_b[0];
    float bs = Fbb[0];
#pragma unroll 8
    for (int k = 0; k < 64; k++) {
        float gv = gp[k], hv = hp[k];
        mu = fmaf(gv, Phi_w[k], mu);
        mu = fmaf(hv, Phi_w[64 + k], mu);
        bs = fmaf(gv, Fbw[k], bs);
        bs = fmaf(hv, Fbw[64 + k], bs);
    }
    float e = __expf(ftanh_(bs));
    float se = e, sem = e * mu;
#pragma unroll
    for (int off = 16; off; off >>= 1) {
        se  += __shfl_xor_sync(0xffffffffu, se, off);
        sem += __shfl_xor_sync(0xffffffffu, sem, off);
    }
    out[128 + 1048576 + b * 32 + i] = __fdividef(e, se);  // betas
    if (i == 0) out[b] = __fdividef(sem, se);             // mean
}

// ===================== launch =====================
extern "C" void kernel_launch(void* const* d_in, const int* in_sizes, int n_in,
                              void* d_out, int out_size) {
    const float* x   = (const float*)d_in[0];
    const float* Uj  = (const float*)d_in[1];
    const float* Ui_ = (const float*)d_in[2];
    const float* Uf  = (const float*)d_in[3];
    const float* Uo  = (const float*)d_in[4];
    const float* Wj  = (const float*)d_in[5];
    const float* Wi_ = (const float*)d_in[6];
    const float* Wf  = (const float*)d_in[7];
    const float* Wo  = (const float*)d_in[8];
    const float* bj  = (const float*)d_in[9];
    const float* bi_ = (const float*)d_in[10];
    const float* bf  = (const float*)d_in[11];
    const float* bo  = (const float*)d_in[12];
    const float* Fa  = (const float*)d_in[13];
    const float* Fab = (const float*)d_in[14];
    const float* Fbw = (const float*)d_in[15];
    const float* Fbb = (const float*)d_in[16];
    const float* Pw  = (const float*)d_in[17];
    const float* Pb  = (const float*)d_in[18];
    float* out = (float*)d_out;

    size_t smem = SM_TOT * sizeof(float);  // ~107 KB
    cudaFuncSetAttribute(lstm_kernel, cudaFuncAttributeMaxDynamicSharedMemorySize, (int)smem);

    lstm_kernel<<<dim3(32, 4), 256, smem>>>(x, Uj, Ui_, Uf, Uo, Wj, Wi_, Wf, Wo,
                                            bj, bi_, bf, bo, Fa, Fab);
    alpha_kernel<<<4096, 256>>>(out);
    head_kernel<<<128, 32>>>(out, Pw, Pb, Fbw, Fbb);
}

// round 3
// speedup vs baseline: 1.4058x; 1.4058x over previous
#include <cuda_runtime.h>

// Problem constants
#define B_DIM 128
#define T_DIM 256
#define D_DIM 32
#define N_DIM 64

// Scratch (device globals: no allocation allowed)
__device__ float g_aBuf[D_DIM * T_DIM * B_DIM];   // [i][t][b] unnormalized alphas
__device__ float g_denBuf[D_DIM * B_DIM];         // [i][b]
__device__ float g_gBuf[B_DIM * D_DIM * N_DIM];   // [b][i][k] g_n (normalized)
__device__ float g_hTBuf[B_DIM * D_DIM * N_DIM];  // [b][i][k] h_T

// ---------------- math helpers ----------------
static __device__ __forceinline__ float fsig(float x) {
    return __fdividef(1.0f, 1.0f + __expf(-x));
}
static __device__ __forceinline__ float ftanh_(float x) {
    float ax = fabsf(x);
    float e = __expf(-2.0f * ax);
    float t = 1.0f - __fdividef(2.0f * e, 1.0f + e);
    return copysignf(t, x);
}
// packed f32x2 fma (Blackwell)
static __device__ __forceinline__ void fma2(unsigned long long& a,
                                            unsigned long long b,
                                            unsigned long long c) {
    asm("fma.rn.f32x2 %0, %1, %2, %0;" : "+l"(a) : "l"(b), "l"(c));
}
static __device__ __forceinline__ unsigned long long pack2(float x) {
    unsigned long long r;
    asm("mov.b64 %0, {%1, %1};" : "=l"(r) : "f"(x));
    return r;
}
static __device__ __forceinline__ unsigned long long packab(float x, float y) {
    unsigned long long r;
    asm("mov.b64 %0, {%1, %2};" : "=l"(r) : "f"(x), "f"(y));
    return r;
}
static __device__ __forceinline__ float2 unpack2(unsigned long long a) {
    float lo, hi;
    asm("mov.b64 {%0, %1}, %2;" : "=f"(lo), "=f"(hi) : "l"(a));
    return make_float2(lo, hi);
}

// ---------------- shared memory layout (float offsets) ----------------
// W' interleaved: [j][kpair(32)][gate(4)][kappa(2)] -> row j = 256 floats = 64 ull2
#define SMW 0          // 64 j * 256 = 16384 floats
#define SMX 16384      // x: 256 t * 32 b = 8192
#define SMH 24576      // h ping-pong: 2 * (64 j * 32 b) = 4096
#define SMS 28672      // sp ping-pong: 2 * 256 = 512
#define SMTOT 29184    // floats -> 116736 bytes

// ===================== Kernel 1: fused LSTM + streamed attention =====================
// grid = (32 i, 4 b-chunks), block = 256 = 8 warps.
// warp w owns k in [8w, 8w+8); lane = bq*4 + p: p -> k-pair (k0 = 8w+2p), bq -> b-quad.
__global__ void __launch_bounds__(256)
lstm_kernel(const float* __restrict__ x,
            const float* __restrict__ Uj, const float* __restrict__ Ui_,
            const float* __restrict__ Uf, const float* __restrict__ Uo,
            const float* __restrict__ Wj, const float* __restrict__ Wi_,
            const float* __restrict__ Wf, const float* __restrict__ Wo,
            const float* __restrict__ bj, const float* __restrict__ bi_,
            const float* __restrict__ bf, const float* __restrict__ bo,
            const float* __restrict__ Fa, const float* __restrict__ Fab) {
    extern __shared__ float sm[];
    const int tid = threadIdx.x;
    const int w   = tid >> 5;
    const int lane = tid & 31;
    const int p   = lane & 3;
    const int bq  = lane >> 2;
    const int i   = blockIdx.x;
    const int b0  = blockIdx.y << 5;
    const int k0  = w * 8 + p * 2;      // first k of this thread's pair
    const int wo  = w * 4 + p;          // global k-pair index 0..31

    // ---- cooperative loads ----
    {
        const float* Wg[4] = {Wj, Wi_, Wf, Wo};
#pragma unroll
        for (int gg = 0; gg < 4; gg++) {
            const float* src = Wg[gg];
            for (int idx = tid; idx < 4096; idx += 256) {
                int j = idx >> 6, k = idx & 63;
                // W'[j][k>>1][g][k&1]
                sm[SMW + j * 256 + (k >> 1) * 8 + gg * 2 + (k & 1)] =
                    src[(j * 32 + i) * 64 + k];
            }
        }
        for (int idx = tid; idx < 8192; idx += 256) {
            int t = idx >> 5, bl = idx & 31;
            sm[SMX + idx] = x[((b0 + bl) * 256 + t) * 32 + i];
        }
        for (int idx = tid; idx < 4096; idx += 256) sm[SMH + idx] = 0.0f;
    }
    __syncthreads();

    // ---- per-thread constants (registers) ----
    unsigned long long bias2[4], u2[4];
    {
        const float* Bg[4] = {bj, bi_, bf, bo};
        const float* Ug[4] = {Uj, Ui_, Uf, Uo};
#pragma unroll
        for (int gg = 0; gg < 4; gg++) {
            float2 bb = *(const float2*)&Bg[gg][i * 64 + k0];
            float2 uu = *(const float2*)&Ug[gg][i * 64 + k0];
            bias2[gg] = packab(bb.x, bb.y);
            u2[gg]    = packab(uu.x, uu.y);
        }
    }
    const float fa0 = Fa[k0 * 32 + i];
    const float fa1 = Fa[(k0 + 1) * 32 + i];
    const float FabV = Fab[i];

    // ---- state ----
    unsigned long long acc[4][4];                 // [gate][b]
    float c[2][4], gacc[2][4], hn[2][4], den[4];  // [kappa][b]
#pragma unroll
    for (int b = 0; b < 4; b++) {
        c[0][b] = c[1][b] = 0.0f;
        gacc[0][b] = gacc[1][b] = 0.0f;
        hn[0][b] = hn[1][b] = 0.0f;
        den[b] = 0.0f;
    }

    const ulonglong2* W2 = (const ulonglong2*)(sm + SMW);  // 16B units; ROW j = 64 ull2
    int cur = 0;

    for (int t = 0; t < 256; t++) {
        // init acc = bias + x*U
        const float4 xv4 = *(const float4*)&sm[SMX + t * 32 + bq * 4];
        unsigned long long xv2[4];
        xv2[0] = pack2(xv4.x); xv2[1] = pack2(xv4.y);
        xv2[2] = pack2(xv4.z); xv2[3] = pack2(xv4.w);
#pragma unroll
        for (int gg = 0; gg < 4; gg++)
#pragma unroll
            for (int b = 0; b < 4; b++) {
                acc[gg][b] = bias2[gg];
                fma2(acc[gg][b], u2[gg], xv2[b]);
            }

        // recurrent matvec: register-tiled outer product over j
        const float* hbase = sm + SMH + cur * 2048;
#pragma unroll 8
        for (int j = 0; j < 64; j++) {
            const float4 h4 = *(const float4*)&hbase[j * 32 + bq * 4];
            unsigned long long h2[4];
            h2[0] = pack2(h4.x); h2[1] = pack2(h4.y);
            h2[2] = pack2(h4.z); h2[3] = pack2(h4.w);
            const ulonglong2 wA = W2[j * 64 + wo * 2];      // gates 0,1 (pair-packed)
            const ulonglong2 wB = W2[j * 64 + wo * 2 + 1];  // gates 2,3
#pragma unroll
            for (int b = 0; b < 4; b++) {
                fma2(acc[0][b], wA.x, h2[b]);
                fma2(acc[1][b], wA.y, h2[b]);
                fma2(acc[2][b], wB.x, h2[b]);
                fma2(acc[3][b], wB.y, h2[b]);
            }
        }

        // gate nonlinearities + state update + alpha partial
        float sp[4];
#pragma unroll
        for (int b = 0; b < 4; b++) {
            float2 jv = unpack2(acc[0][b]);
            float2 iv = unpack2(acc[1][b]);
            float2 fv = unpack2(acc[2][b]);
            float2 ov = unpack2(acc[3][b]);
            {
                float jj = ftanh_(jv.x), ii = fsig(iv.x), ff = fsig(fv.x), oo = fsig(ov.x);
                float cn = fmaf(c[0][b], ff, ii * jj);
                c[0][b] = cn;
                hn[0][b] = oo * ftanh_(cn);
            }
            {
                float jj = ftanh_(jv.y), ii = fsig(iv.y), ff = fsig(fv.y), oo = fsig(ov.y);
                float cn = fmaf(c[1][b], ff, ii * jj);
                c[1][b] = cn;
                hn[1][b] = oo * ftanh_(cn);
            }
            sp[b] = fmaf(hn[0][b], fa0, hn[1][b] * fa1);
        }
        // reduce alpha partials over the 4 p-lanes sharing this b-quad
#pragma unroll
        for (int b = 0; b < 4; b++) {
            sp[b] += __shfl_xor_sync(0xffffffffu, sp[b], 1);
            sp[b] += __shfl_xor_sync(0xffffffffu, sp[b], 2);
        }
        if (p == 0)
            *(float4*)&sm[SMS + (t & 1) * 256 + w * 32 + bq * 4] =
                make_float4(sp[0], sp[1], sp[2], sp[3]);

        // write h_next (ping-pong buffer)
        float* hnext = sm + SMH + (cur ^ 1) * 2048;
        *(float4*)&hnext[k0 * 32 + bq * 4] =
            make_float4(hn[0][0], hn[0][1], hn[0][2], hn[0][3]);
        *(float4*)&hnext[(k0 + 1) * 32 + bq * 4] =
            make_float4(hn[1][0], hn[1][1], hn[1][2], hn[1][3]);

        __syncthreads();  // single barrier per step

        // alpha score -> av; accumulate denominator and g_n
        float s0 = FabV, s1 = FabV, s2 = FabV, s3 = FabV;
        const float* spb = sm + SMS + (t & 1) * 256;
#pragma unroll
        for (int ww = 0; ww < 8; ww++) {
            float4 v = *(const float4*)&spb[ww * 32 + bq * 4];
            s0 += v.x; s1 += v.y; s2 += v.z; s3 += v.w;
        }
        float av[4];
        av[0] = __expf(ftanh_(s0));
        av[1] = __expf(ftanh_(s1));
        av[2] = __expf(ftanh_(s2));
        av[3] = __expf(ftanh_(s3));
#pragma unroll
        for (int b = 0; b < 4; b++) {
            den[b] += av[b];
            gacc[0][b] = fmaf(av[b], hn[0][b], gacc[0][b]);
            gacc[1][b] = fmaf(av[b], hn[1][b], gacc[1][b]);
        }
        if (w == 0 && p == 0)
            *(float4*)&g_aBuf[(i * 256 + t) * 128 + b0 + bq * 4] =
                make_float4(av[0], av[1], av[2], av[3]);

        cur ^= 1;
    }

    // ---- epilogue ----
#pragma unroll
    for (int b = 0; b < 4; b++) {
        int bg = b0 + bq * 4 + b;
        float invd = __fdividef(1.0f, den[b]);
        g_gBuf[(bg * 32 + i) * 64 + k0]      = gacc[0][b] * invd;
        g_gBuf[(bg * 32 + i) * 64 + k0 + 1]  = gacc[1][b] * invd;
        g_hTBuf[(bg * 32 + i) * 64 + k0]     = hn[0][b];
        g_hTBuf[(bg * 32 + i) * 64 + k0 + 1] = hn[1][b];
    }
    if (w == 0 && p == 0)
        *(float4*)&g_denBuf[i * 128 + b0 + bq * 4] =
            make_float4(den[0], den[1], den[2], den[3]);
}

// ===================== Kernel 2: normalize alphas into [B,T,D] =====================
__global__ void alpha_kernel(float* __restrict__ out) {
    int idx = blockIdx.x * 256 + threadIdx.x;  // 0 .. 1048575
    int b = idx >> 13;
    int r = idx & 8191;
    int t = r >> 5;
    int i = r & 31;
    float a = g_aBuf[(i * 256 + t) * 128 + b];
    float d = g_denBuf[i * 128 + b];
    out[128 + idx] = __fdividef(a, d);
}

// ===================== Kernel 3: output head =====================
__global__ void head_kernel(float* __restrict__ out,
                            const float* __restrict__ Phi_w, const float* __restrict__ Phi_b,
                            const float* __restrict__ Fbw, const float* __restrict__ Fbb) {
    int b = blockIdx.x;
    int i = threadIdx.x;
    const float* gp = g_gBuf + (b * 32 + i) * 64;
    const float* hp = g_hTBuf + (b * 32 + i) * 64;
    float mu = Phi_b[0];
    float bs = Fbb[0];
#pragma unroll 8
    for (int k = 0; k < 64; k++) {
        float gv = gp[k], hv = hp[k];
        mu = fmaf(gv, Phi_w[k], mu);
        mu = fmaf(hv, Phi_w[64 + k], mu);
        bs = fmaf(gv, Fbw[k], bs);
        bs = fmaf(hv, Fbw[64 + k], bs);
    }
    float e = __expf(ftanh_(bs));
    float se = e, sem = e * mu;
#pragma unroll
    for (int off = 16; off; off >>= 1) {
        se  += __shfl_xor_sync(0xffffffffu, se, off);
        sem += __shfl_xor_sync(0xffffffffu, sem, off);
    }
    out[128 + 1048576 + b * 32 + i] = __fdividef(e, se);  // betas
    if (i == 0) out[b] = __fdividef(sem, se);             // mean
}

// ===================== launch =====================
extern "C" void kernel_launch(void* const* d_in, const int* in_sizes, int n_in,
                              void* d_out, int out_size) {
    const float* x   = (const float*)d_in[0];
    const float* Uj  = (const float*)d_in[1];
    const float* Ui_ = (const float*)d_in[2];
    const float* Uf  = (const float*)d_in[3];
    const float* Uo  = (const float*)d_in[4];
    const float* Wj  = (const float*)d_in[5];
    const float* Wi_ = (const float*)d_in[6];
    const float* Wf  = (const float*)d_in[7];
    const float* Wo  = (const float*)d_in[8];
    const float* bj  = (const float*)d_in[9];
    const float* bi_ = (const float*)d_in[10];
    const float* bf  = (const float*)d_in[11];
    const float* bo  = (const float*)d_in[12];
    const float* Fa  = (const float*)d_in[13];
    const float* Fab = (const float*)d_in[14];
    const float* Fbw = (const float*)d_in[15];
    const float* Fbb = (const float*)d_in[16];
    const float* Pw  = (const float*)d_in[17];
    const float* Pb  = (const float*)d_in[18];
    float* out = (float*)d_out;

    size_t smem = SMTOT * sizeof(float);  // ~114 KB
    cudaFuncSetAttribute(lstm_kernel, cudaFuncAttributeMaxDynamicSharedMemorySize, (int)smem);

    lstm_kernel<<<dim3(32, 4), 256, smem>>>(x, Uj, Ui_, Uf, Uo, Wj, Wi_, Wf, Wo,
                                            bj, bi_, bf, bo, Fa, Fab);
    alpha_kernel<<<4096, 256>>>(out);
    head_kernel<<<128, 32>>>(out, Pw, Pb, Fbw, Fbb);
}

// round 4
// speedup vs baseline: 1.4342x; 1.0202x over previous
#include <cuda_runtime.h>

// Problem constants
#define B_DIM 128
#define T_DIM 256
#define D_DIM 32
#define N_DIM 64

// Scratch (device globals: no allocation allowed)
__device__ float g_aBuf[D_DIM * T_DIM * B_DIM];   // [i][t][b] unnormalized alphas
__device__ float g_denBuf[D_DIM * B_DIM];         // [i][b]
__device__ float g_gBuf[B_DIM * D_DIM * N_DIM];   // [b][i][k] g_n (normalized)
__device__ float g_hTBuf[B_DIM * D_DIM * N_DIM];  // [b][i][k] h_T

// ---------------- math helpers ----------------
static __device__ __forceinline__ float fsig(float x) {
    return __fdividef(1.0f, 1.0f + __expf(-x));
}
static __device__ __forceinline__ float ftanh_(float x) {
    float ax = fabsf(x);
    float e = __expf(-2.0f * ax);
    float t = 1.0f - __fdividef(2.0f * e, 1.0f + e);
    return copysignf(t, x);
}
// packed f32x2 fma (Blackwell)
static __device__ __forceinline__ void fma2(unsigned long long& a,
                                            unsigned long long b,
                                            unsigned long long c) {
    asm("fma.rn.f32x2 %0, %1, %2, %0;" : "+l"(a) : "l"(b), "l"(c));
}
static __device__ __forceinline__ unsigned long long pack2(float x) {
    unsigned long long r;
    asm("mov.b64 %0, {%1, %1};" : "=l"(r) : "f"(x));
    return r;
}
static __device__ __forceinline__ unsigned long long packab(float x, float y) {
    unsigned long long r;
    asm("mov.b64 %0, {%1, %2};" : "=l"(r) : "f"(x), "f"(y));
    return r;
}
static __device__ __forceinline__ float2 unpack2(unsigned long long a) {
    float lo, hi;
    asm("mov.b64 {%0, %1}, %2;" : "=f"(lo), "=f"(hi) : "l"(a));
    return make_float2(lo, hi);
}

// ---------------- shared memory layout (float offsets) ----------------
// W' interleaved: [j][kpair(32)][gate(4)][kappa(2)] -> row j = 256 floats = 64 ull2
#define SMW 0          // 64 j * 256 = 16384 floats
#define SMX 16384      // x: 256 t * 32 b = 8192
#define SMH 24576      // h ping-pong: 2 * (64 j * 32 b) = 4096
#define SMS 28672      // sp ping-pong: 2 * (16 w * 32 b) = 1024
#define SMTOT 29696    // floats -> 118784 bytes

// ===================== Kernel 1: fused LSTM + streamed attention =====================
// grid = (32 i, 4 b-chunks), block = 512 = 16 warps (4 per SMSP).
// warp w owns k in [4w, 4w+4); lane = bq*2 + p: p -> k-pair (k0 = 4w+2p), bq -> b-pair.
__global__ void __launch_bounds__(512)
lstm_kernel(const float* __restrict__ x,
            const float* __restrict__ Uj, const float* __restrict__ Ui_,
            const float* __restrict__ Uf, const float* __restrict__ Uo,
            const float* __restrict__ Wj, const float* __restrict__ Wi_,
            const float* __restrict__ Wf, const float* __restrict__ Wo,
            const float* __restrict__ bj, const float* __restrict__ bi_,
            const float* __restrict__ bf, const float* __restrict__ bo,
            const float* __restrict__ Fa, const float* __restrict__ Fab) {
    extern __shared__ float sm[];
    const int tid  = threadIdx.x;
    const int w    = tid >> 5;
    const int lane = tid & 31;
    const int p    = lane & 1;
    const int bq   = lane >> 1;
    const int i    = blockIdx.x;
    const int b0   = blockIdx.y << 5;
    const int k0   = w * 4 + p * 2;        // first k of this thread's pair
    const int wq   = w * 4 + p * 2;        // ull2 base offset within row j (== 2*kpair)

    // ---- cooperative loads ----
    {
        const float* Wg[4] = {Wj, Wi_, Wf, Wo};
#pragma unroll
        for (int gg = 0; gg < 4; gg++) {
            const float* src = Wg[gg];
            for (int idx = tid; idx < 4096; idx += 512) {
                int j = idx >> 6, k = idx & 63;
                // W'[j][k>>1][g][k&1]
                sm[SMW + j * 256 + (k >> 1) * 8 + gg * 2 + (k & 1)] =
                    src[(j * 32 + i) * 64 + k];
            }
        }
        for (int idx = tid; idx < 8192; idx += 512) {
            int t = idx >> 5, bl = idx & 31;
            sm[SMX + idx] = x[((b0 + bl) * 256 + t) * 32 + i];
        }
        for (int idx = tid; idx < 4096; idx += 512) sm[SMH + idx] = 0.0f;
    }
    __syncthreads();

    // ---- per-thread constants (registers) ----
    unsigned long long bias2[4], u2[4];
    {
        const float* Bg[4] = {bj, bi_, bf, bo};
        const float* Ug[4] = {Uj, Ui_, Uf, Uo};
#pragma unroll
        for (int gg = 0; gg < 4; gg++) {
            float2 bb = *(const float2*)&Bg[gg][i * 64 + k0];
            float2 uu = *(const float2*)&Ug[gg][i * 64 + k0];
            bias2[gg] = packab(bb.x, bb.y);
            u2[gg]    = packab(uu.x, uu.y);
        }
    }
    const float fa0 = Fa[k0 * 32 + i];
    const float fa1 = Fa[(k0 + 1) * 32 + i];
    const float FabV = Fab[i];

    // ---- state ----
    unsigned long long acc[4][2];                 // [gate][b]
    float c[2][2], gacc[2][2], hn[2][2], den[2];  // [kappa][b]
#pragma unroll
    for (int b = 0; b < 2; b++) {
        c[0][b] = c[1][b] = 0.0f;
        gacc[0][b] = gacc[1][b] = 0.0f;
        hn[0][b] = hn[1][b] = 0.0f;
        den[b] = 0.0f;
    }

    const ulonglong2* W2 = (const ulonglong2*)(sm + SMW);  // 16B units; ROW j = 64 ull2
    int cur = 0;

    for (int t = 0; t < 256; t++) {
        // init acc = bias + x*U
        const float2 xv = *(const float2*)&sm[SMX + t * 32 + bq * 2];
        unsigned long long xv2[2];
        xv2[0] = pack2(xv.x);
        xv2[1] = pack2(xv.y);
#pragma unroll
        for (int gg = 0; gg < 4; gg++)
#pragma unroll
            for (int b = 0; b < 2; b++) {
                acc[gg][b] = bias2[gg];
                fma2(acc[gg][b], u2[gg], xv2[b]);
            }

        // recurrent matvec: register-tiled outer product over j
        const float* hbase = sm + SMH + cur * 2048;
#pragma unroll 8
        for (int j = 0; j < 64; j++) {
            const float2 h2f = *(const float2*)&hbase[j * 32 + bq * 2];
            unsigned long long h2[2];
            h2[0] = pack2(h2f.x);
            h2[1] = pack2(h2f.y);
            const ulonglong2 wA = W2[j * 64 + wq];      // gates 0,1 (kappa-packed)
            const ulonglong2 wB = W2[j * 64 + wq + 1];  // gates 2,3
#pragma unroll
            for (int b = 0; b < 2; b++) {
                fma2(acc[0][b], wA.x, h2[b]);
                fma2(acc[1][b], wA.y, h2[b]);
                fma2(acc[2][b], wB.x, h2[b]);
                fma2(acc[3][b], wB.y, h2[b]);
            }
        }

        // gate nonlinearities + state update + alpha partial
        float sp[2];
#pragma unroll
        for (int b = 0; b < 2; b++) {
            float2 jv = unpack2(acc[0][b]);
            float2 iv = unpack2(acc[1][b]);
            float2 fv = unpack2(acc[2][b]);
            float2 ov = unpack2(acc[3][b]);
            {
                float jj = ftanh_(jv.x), ii = fsig(iv.x), ff = fsig(fv.x), oo = fsig(ov.x);
                float cn = fmaf(c[0][b], ff, ii * jj);
                c[0][b] = cn;
                hn[0][b] = oo * ftanh_(cn);
            }
            {
                float jj = ftanh_(jv.y), ii = fsig(iv.y), ff = fsig(fv.y), oo = fsig(ov.y);
                float cn = fmaf(c[1][b], ff, ii * jj);
                c[1][b] = cn;
                hn[1][b] = oo * ftanh_(cn);
            }
            sp[b] = fmaf(hn[0][b], fa0, hn[1][b] * fa1);
        }
        // reduce alpha partials over the 2 p-lanes sharing this b-pair
        sp[0] += __shfl_xor_sync(0xffffffffu, sp[0], 1);
        sp[1] += __shfl_xor_sync(0xffffffffu, sp[1], 1);
        if (p == 0)
            *(float2*)&sm[SMS + (t & 1) * 512 + w * 32 + bq * 2] =
                make_float2(sp[0], sp[1]);

        // write h_next (ping-pong buffer)
        float* hnext = sm + SMH + (cur ^ 1) * 2048;
        *(float2*)&hnext[k0 * 32 + bq * 2]       = make_float2(hn[0][0], hn[0][1]);
        *(float2*)&hnext[(k0 + 1) * 32 + bq * 2] = make_float2(hn[1][0], hn[1][1]);

        __syncthreads();  // single barrier per step

        // alpha score -> av; accumulate denominator and g_n
        float s0 = FabV, s1 = FabV;
        const float* spb = sm + SMS + (t & 1) * 512;
#pragma unroll
        for (int ww = 0; ww < 16; ww++) {
            float2 v = *(const float2*)&spb[ww * 32 + bq * 2];
            s0 += v.x;
            s1 += v.y;
        }
        float av[2];
        av[0] = __expf(ftanh_(s0));
        av[1] = __expf(ftanh_(s1));
#pragma unroll
        for (int b = 0; b < 2; b++) {
            den[b] += av[b];
            gacc[0][b] = fmaf(av[b], hn[0][b], gacc[0][b]);
            gacc[1][b] = fmaf(av[b], hn[1][b], gacc[1][b]);
        }
        if (w == 0 && p == 0)
            *(float2*)&g_aBuf[(i * 256 + t) * 128 + b0 + bq * 2] =
                make_float2(av[0], av[1]);

        cur ^= 1;
    }

    // ---- epilogue ----
#pragma unroll
    for (int b = 0; b < 2; b++) {
        int bg = b0 + bq * 2 + b;
        float invd = __fdividef(1.0f, den[b]);
        g_gBuf[(bg * 32 + i) * 64 + k0]      = gacc[0][b] * invd;
        g_gBuf[(bg * 32 + i) * 64 + k0 + 1]  = gacc[1][b] * invd;
        g_hTBuf[(bg * 32 + i) * 64 + k0]     = hn[0][b];
        g_hTBuf[(bg * 32 + i) * 64 + k0 + 1] = hn[1][b];
    }
    if (w == 0 && p == 0)
        *(float2*)&g_denBuf[i * 128 + b0 + bq * 2] = make_float2(den[0], den[1]);
}

// ===================== Kernel 2: normalize alphas into [B,T,D] =====================
__global__ void alpha_kernel(float* __restrict__ out) {
    int idx = blockIdx.x * 256 + threadIdx.x;  // 0 .. 1048575
    int b = idx >> 13;
    int r = idx & 8191;
    int t = r >> 5;
    int i = r & 31;
    float a = g_aBuf[(i * 256 + t) * 128 + b];
    float d = g_denBuf[i * 128 + b];
    out[128 + idx] = __fdividef(a, d);
}

// ===================== Kernel 3: output head =====================
__global__ void head_kernel(float* __restrict__ out,
                            const float* __restrict__ Phi_w, const float* __restrict__ Phi_b,
                            const float* __restrict__ Fbw, const float* __restrict__ Fbb) {
    int b = blockIdx.x;
    int i = threadIdx.x;
    const float* gp = g_gBuf + (b * 32 + i) * 64;
    const float* hp = g_hTBuf + (b * 32 + i) * 64;
    float mu = Phi_b[0];
    float bs = Fbb[0];
#pragma unroll 8
    for (int k = 0; k < 64; k++) {
        float gv = gp[k], hv = hp[k];
        mu = fmaf(gv, Phi_w[k], mu);
        mu = fmaf(hv, Phi_w[64 + k], mu);
        bs = fmaf(gv, Fbw[k], bs);
        bs = fmaf(hv, Fbw[64 + k], bs);
    }
    float e = __expf(ftanh_(bs));
    float se = e, sem = e * mu;
#pragma unroll
    for (int off = 16; off; off >>= 1) {
        se  += __shfl_xor_sync(0xffffffffu, se, off);
        sem += __shfl_xor_sync(0xffffffffu, sem, off);
    }
    out[128 + 1048576 + b * 32 + i] = __fdividef(e, se);  // betas
    if (i == 0) out[b] = __fdividef(sem, se);             // mean
}

// ===================== launch =====================
extern "C" void kernel_launch(void* const* d_in, const int* in_sizes, int n_in,
                              void* d_out, int out_size) {
    const float* x   = (const float*)d_in[0];
    const float* Uj  = (const float*)d_in[1];
    const float* Ui_ = (const float*)d_in[2];
    const float* Uf  = (const float*)d_in[3];
    const float* Uo  = (const float*)d_in[4];
    const float* Wj  = (const float*)d_in[5];
    const float* Wi_ = (const float*)d_in[6];
    const float* Wf  = (const float*)d_in[7];
    const float* Wo  = (const float*)d_in[8];
    const float* bj  = (const float*)d_in[9];
    const float* bi_ = (const float*)d_in[10];
    const float* bf  = (const float*)d_in[11];
    const float* bo  = (const float*)d_in[12];
    const float* Fa  = (const float*)d_in[13];
    const float* Fab = (const float*)d_in[14];
    const float* Fbw = (const float*)d_in[15];
    const float* Fbb = (const float*)d_in[16];
    const float* Pw  = (const float*)d_in[17];
    const float* Pb  = (const float*)d_in[18];
    float* out = (float*)d_out;

    size_t smem = SMTOT * sizeof(float);  // ~116 KB
    cudaFuncSetAttribute(lstm_kernel, cudaFuncAttributeMaxDynamicSharedMemorySize, (int)smem);

    lstm_kernel<<<dim3(32, 4), 512, smem>>>(x, Uj, Ui_, Uf, Uo, Wj, Wi_, Wf, Wo,
                                            bj, bi_, bf, bo, Fa, Fab);
    alpha_kernel<<<4096, 256>>>(out);
    head_kernel<<<128, 32>>>(out, Pw, Pb, Fbw, Fbb);
}